// round 6
// baseline (speedup 1.0000x reference)
#include <cuda_runtime.h>
#include <cstdint>

// ---------------------------------------------------------------------------
// Problem constants
// ---------------------------------------------------------------------------
#define BATCH   1024
#define D_SZ    384
#define K_WIDE  (D_SZ * D_SZ)      // 147456
#define N_OUT   (2 * D_SZ)         // 768
#define OUT_STR (4 * D_SZ)         // 1536

// ---------------------------------------------------------------------------
// Wide-path GEMM config: M=1024 N=768 K=147456, A = hs x ht generated on-fly
// ---------------------------------------------------------------------------
#define BM      128
#define BN      128
#define BKC     32                  // k-floats per chunk
#define KSPLIT  3
#define KSLICE  (K_WIDE / KSPLIT)   // 49152 = 128 i-values
#define IPG     8                   // i-values per hs staging group
#define NCH     (KSLICE / BKC)      // 1536 chunks per CTA
#define LDT     36                  // row stride words: BKC=32 + 4 pad (conflict-free)
#define NTH     512
#define NBUF    3

#define B_WORDS   (BN * LDT)            // per B buffer
#define HTS_WORDS (BM * LDT)
#define HSS_WORDS (IPG * BM)
#define SMEM_WORDS (NBUF * B_WORDS + HTS_WORDS + HSS_WORDS)
#define SMEM_BYTES (SMEM_WORDS * 4)     // ~78 KB -> dynamic smem

__device__ __forceinline__ void cp_async16(uint32_t dst, const void* src) {
    asm volatile("cp.async.cg.shared.global [%0], [%1], 16;" :: "r"(dst), "l"(src) : "memory");
}
__device__ __forceinline__ void cp_commit() {
    asm volatile("cp.async.commit_group;" ::: "memory");
}
__device__ __forceinline__ void cp_wait1() {
    asm volatile("cp.async.wait_group 1;" ::: "memory");
}
__device__ __forceinline__ void bar_sync(int id, int cnt) {
    asm volatile("bar.sync %0, %1;" :: "r"(id), "r"(cnt) : "memory");
}
__device__ __forceinline__ uint32_t smem_u32(const void* p) {
    uint32_t a;
    asm("{ .reg .u64 t; cvta.to.shared.u64 t, %1; cvt.u32.u64 %0, t; }" : "=r"(a) : "l"(p));
    return a;
}
__device__ __forceinline__ float f2tf32(float x) {          // round-to-nearest tf32
    unsigned r;
    asm("cvt.rna.tf32.f32 %0, %1;" : "=r"(r) : "f"(x));
    return __uint_as_float(r);
}

// m16n8k8 tf32 mma (A pre-rounded rna; B HW-truncated from fp32 bits)
__device__ __forceinline__ void mma_tf32(float c[4], const float a[4], float b0, float b1) {
    asm volatile(
        "mma.sync.aligned.m16n8k8.row.col.f32.tf32.tf32.f32 "
        "{%0,%1,%2,%3}, {%4,%5,%6,%7}, {%8,%9}, {%0,%1,%2,%3};\n"
        : "+f"(c[0]), "+f"(c[1]), "+f"(c[2]), "+f"(c[3])
        : "r"(__float_as_uint(a[0])), "r"(__float_as_uint(a[1])),
          "r"(__float_as_uint(a[2])), "r"(__float_as_uint(a[3])),
          "r"(__float_as_uint(b0)), "r"(__float_as_uint(b1)));
}

// ---------------------------------------------------------------------------
// Deep path (passed R1, unchanged):  g = [hs|ht] @ W_L^T + b_L -> out[:,0:768]
// Also initializes out[:,768:1536] = b_L2 for the wide kernel's atomics.
// ---------------------------------------------------------------------------
#define DBM 64
#define DBN 64
#define DBK 16

__global__ __launch_bounds__(256)
void deep_kernel(const float* __restrict__ hs, const float* __restrict__ ht,
                 const float* __restrict__ WL, const float* __restrict__ bL,
                 const float* __restrict__ bL2, float* __restrict__ out)
{
    __shared__ float Xs[DBK][DBM + 8];
    __shared__ float Ws[DBK][DBN + 8];

    const int tid = threadIdx.x;
    const int tx  = tid & 15;
    const int ty  = tid >> 4;
    const int m0  = blockIdx.x * DBM;
    const int n0  = blockIdx.y * DBN;

    float acc[4][4];
#pragma unroll
    for (int i = 0; i < 4; ++i)
#pragma unroll
        for (int j = 0; j < 4; ++j) acc[i][j] = 0.f;

    for (int k0 = 0; k0 < 2 * D_SZ; k0 += DBK) {
        __syncthreads();
#pragma unroll
        for (int q = 0; q < 4; ++q) {
            int e  = tid + 256 * q;
            int kk = e & 15;
            int mm = e >> 4;
            int gk = k0 + kk;
            float xv = (gk < D_SZ) ? hs[(m0 + mm) * D_SZ + gk]
                                   : ht[(m0 + mm) * D_SZ + (gk - D_SZ)];
            Xs[kk][mm] = xv;
            Ws[kk][mm] = WL[(size_t)(n0 + mm) * (2 * D_SZ) + gk];
        }
        __syncthreads();
#pragma unroll
        for (int kk = 0; kk < DBK; ++kk) {
            float4 av = *(const float4*)&Xs[kk][ty * 4];
            float4 bv = *(const float4*)&Ws[kk][tx * 4];
            float a[4] = {av.x, av.y, av.z, av.w};
            float b[4] = {bv.x, bv.y, bv.z, bv.w};
#pragma unroll
            for (int i = 0; i < 4; ++i)
#pragma unroll
                for (int j = 0; j < 4; ++j) acc[i][j] += a[i] * b[j];
        }
    }

#pragma unroll
    for (int i = 0; i < 4; ++i) {
        int row = m0 + ty * 4 + i;
#pragma unroll
        for (int j = 0; j < 4; ++j) {
            int col = n0 + tx * 4 + j;
            out[(size_t)row * OUT_STR + col]         = acc[i][j] + bL[col];
            out[(size_t)row * OUT_STR + N_OUT + col] = bL2[col];
        }
    }
}

// ---------------------------------------------------------------------------
// Wide kernel: 512 threads = 16 warps (4m x 4n), warp tile 32x32.
//
// n-group decoupling (this round's change): group g = warps 4g..4g+3 (threads
// [128g,128g+128)) consumes ONLY B rows [32g,32g+32). Each group stages its
// own rows and synchronizes per-chunk with a private named barrier
// bar.sync(1+g,128), so a stalled group no longer paces the other three.
// Full __syncthreads only at Hss/Hts staging epochs (every 8 chunks), where
// cross-group shared data is rewritten.
//
// Ring safety (per group): at iter ch the group writes buf((ch+2)%3), which
// only its own warps read, last at iter ch-1; the group's barrier at iter ch
// (or the full sync on 8-chunk epochs) bounds its warps' drift.
// cp.async visibility: each thread waits its own groups, then the group
// barrier orders those writes for the group's consumers.
// ---------------------------------------------------------------------------
__global__ __launch_bounds__(NTH, 1)
void wide_kernel(const float* __restrict__ hs, const float* __restrict__ ht,
                 const float* __restrict__ W2, float* __restrict__ out)
{
    extern __shared__ __align__(16) float smem[];
    float* Bsm = smem;                          // NBUF * BN * LDT
    float* Hts = smem + NBUF * B_WORDS;         // BM * LDT
    float* Hss = Hts + HTS_WORDS;               // IPG * BM

    const int tid  = threadIdx.x;
    const int lane = tid & 31;
    const int warp = tid >> 5;
    const int wm = (warp & 3) * 32;     // warp m offset
    const int wn = (warp >> 2) * 32;    // warp n offset
    const int r  = lane >> 2;           // 0..7
    const int c  = lane & 3;            // 0..3

    const int grp  = warp >> 2;         // n-group 0..3 (consumes B rows [32g,32g+32))
    const int gtid = tid & 127;         // thread index within group

    const int m0 = blockIdx.x * BM;
    const int n0 = blockIdx.y * BN;
    const int z  = blockIdx.z;
    const size_t kbase = (size_t)z * KSLICE;
    const int i0 = z * (KSLICE / D_SZ);

    // per-thread B staging coords WITHIN this thread's group rows:
    // 32 rows x 8 float4-segs = 256 segs / 128 group threads = 2 each
    const int srow0 = grp * 32 + ((gtid * 2)     >> 3);
    const int skv0  = ((gtid * 2)     & 7) * 4;
    const int srow1 = grp * 32 + ((gtid * 2 + 1) >> 3);
    const int skv1  = ((gtid * 2 + 1) & 7) * 4;
    const uint32_t sB = smem_u32(Bsm);

    float acc[2][4][4];
#pragma unroll
    for (int mi = 0; mi < 2; ++mi)
#pragma unroll
        for (int ni = 0; ni < 4; ++ni)
#pragma unroll
            for (int q = 0; q < 4; ++q) acc[mi][ni][q] = 0.f;

    float htr[4][2][4];   // ht fragments [kstep][mi][frag]

    // ---- prologue: issue chunks 0 and 1 (jc=0, i_loc=pc) ----
#pragma unroll
    for (int pc = 0; pc < 2; ++pc) {
        size_t gcol = kbase + (size_t)pc * D_SZ;
        uint32_t dbase = sB + (uint32_t)(pc * B_WORDS) * 4;
        cp_async16(dbase + (uint32_t)(srow0 * LDT + skv0) * 4,
                   W2 + (size_t)(n0 + srow0) * K_WIDE + gcol + skv0);
        cp_async16(dbase + (uint32_t)(srow1 * LDT + skv1) * 4,
                   W2 + (size_t)(n0 + srow1) * K_WIDE + gcol + skv1);
        cp_commit();
    }

    int buf = 0, pbuf = 2;   // compute buffer; prefetch buffer (= buf+2 mod 3)

#pragma unroll 1
    for (int ch = 0; ch < NCH; ++ch) {
        cp_wait1();          // this thread's chunk-ch copies complete

        if ((ch & 7) == 0) {
            // epoch: restage Hss (and Hts every 128 chunks) under full syncs
            __syncthreads();                // all groups done reading Hss/Hts & B(ch-1)
            const int jc = ch >> 7;
            const int ib = (ch >> 3) & 15;
            if ((ch & 127) == 0) {
#pragma unroll
                for (int s = 0; s < 2; ++s) {
                    int seg = tid * 2 + s;
                    int row = seg >> 3;
                    int kv  = (seg & 7) * 4;
                    float4 v = *(const float4*)(ht + (size_t)(m0 + row) * D_SZ + jc * BKC + kv);
                    *(float4*)&Hts[row * LDT + kv] = v;
                }
            }
#pragma unroll
            for (int s = 0; s < 2; ++s) {
                int e  = tid + NTH * s;
                int ii = e >> 7;
                int m  = e & 127;
                Hss[ii * BM + m] = __ldg(hs + (size_t)(m0 + m) * D_SZ + i0 + ib * IPG + ii);
            }
            __syncthreads();                // staged data + B(ch) visible to all
            if ((ch & 127) == 0) {
#pragma unroll
                for (int ks = 0; ks < 4; ++ks)
#pragma unroll
                    for (int mi = 0; mi < 2; ++mi) {
                        int mrow = wm + mi * 16;
                        htr[ks][mi][0] = Hts[(mrow + r)     * LDT + ks * 8 + c];
                        htr[ks][mi][1] = Hts[(mrow + r + 8) * LDT + ks * 8 + c];
                        htr[ks][mi][2] = Hts[(mrow + r)     * LDT + ks * 8 + c + 4];
                        htr[ks][mi][3] = Hts[(mrow + r + 8) * LDT + ks * 8 + c + 4];
                    }
            }
        } else {
            // group-private barrier: orders this group's B(ch) staging writes
            // before its own reads, and bounds drift within the group only
            bar_sync(1 + grp, 128);
        }

        // ---- compute chunk ch from Bsm[buf] (this warp: B rows wn..wn+31) ----
        {
            const float* Bb = Bsm + buf * B_WORDS;
            const int ii = ch & 7;
            float hsv[2][2];
            hsv[0][0] = Hss[ii * BM + wm + r];
            hsv[0][1] = Hss[ii * BM + wm + r + 8];
            hsv[1][0] = Hss[ii * BM + wm + 16 + r];
            hsv[1][1] = Hss[ii * BM + wm + 16 + r + 8];

#pragma unroll
            for (int ks = 0; ks < 4; ++ks) {
                float a[2][4];
#pragma unroll
                for (int mi = 0; mi < 2; ++mi) {
                    a[mi][0] = f2tf32(hsv[mi][0] * htr[ks][mi][0]);
                    a[mi][1] = f2tf32(hsv[mi][1] * htr[ks][mi][1]);
                    a[mi][2] = f2tf32(hsv[mi][0] * htr[ks][mi][2]);
                    a[mi][3] = f2tf32(hsv[mi][1] * htr[ks][mi][3]);
                }
#pragma unroll
                for (int ni = 0; ni < 4; ++ni) {
                    int nrow = wn + ni * 8 + r;
                    float b0 = Bb[nrow * LDT + ks * 8 + c];
                    float b1 = Bb[nrow * LDT + ks * 8 + c + 4];
                    mma_tf32(acc[0][ni], a[0], b0, b1);
                    mma_tf32(acc[1][ni], a[1], b0, b1);
                }
            }
        }

        // ---- issue chunk ch+2 into pbuf (group's own rows; safe per header) ----
        if (ch + 2 < NCH) {
            int cn    = ch + 2;
            int jcn   = cn >> 7;
            int ilocn = ((cn >> 3) & 15) * IPG + (cn & 7);
            size_t gcol = kbase + (size_t)ilocn * D_SZ + jcn * BKC;
            uint32_t dbase = sB + (uint32_t)(pbuf * B_WORDS) * 4;
            cp_async16(dbase + (uint32_t)(srow0 * LDT + skv0) * 4,
                       W2 + (size_t)(n0 + srow0) * K_WIDE + gcol + skv0);
            cp_async16(dbase + (uint32_t)(srow1 * LDT + skv1) * 4,
                       W2 + (size_t)(n0 + srow1) * K_WIDE + gcol + skv1);
        }
        cp_commit();   // exactly one group per iteration (possibly empty)

        buf  = (buf  == NBUF - 1) ? 0 : buf + 1;
        pbuf = (pbuf == NBUF - 1) ? 0 : pbuf + 1;
    }

    // ---- epilogue: atomic accumulate onto bias-initialized out[:,768:1536] ----
#pragma unroll
    for (int mi = 0; mi < 2; ++mi) {
#pragma unroll
        for (int ni = 0; ni < 4; ++ni) {
            int row = m0 + wm + mi * 16 + r;
            int col = N_OUT + n0 + wn + ni * 8 + 2 * c;
            float* p0 = &out[(size_t)row * OUT_STR + col];
            atomicAdd(p0,     acc[mi][ni][0]);
            atomicAdd(p0 + 1, acc[mi][ni][1]);
            float* p1 = &out[(size_t)(row + 8) * OUT_STR + col];
            atomicAdd(p1,     acc[mi][ni][2]);
            atomicAdd(p1 + 1, acc[mi][ni][3]);
        }
    }
}

// ---------------------------------------------------------------------------
extern "C" void kernel_launch(void* const* d_in, const int* in_sizes, int n_in,
                              void* d_out, int out_size)
{
    const float* hs  = (const float*)d_in[0];
    const float* ht  = (const float*)d_in[1];
    const float* WL  = (const float*)d_in[2];
    const float* bL  = (const float*)d_in[3];
    const float* W2  = (const float*)d_in[4];
    const float* bL2 = (const float*)d_in[5];
    float* out = (float*)d_out;

    // deep path + bias init of wide region (same-stream ordering -> graph edge)
    deep_kernel<<<dim3(BATCH / DBM, N_OUT / DBN), 256>>>(hs, ht, WL, bL, bL2, out);

    // dynamic smem (~78 KB > 48 KB static limit); attribute set is not an alloc
    cudaFuncSetAttribute(wide_kernel, cudaFuncAttributeMaxDynamicSharedMemorySize, SMEM_BYTES);

    // wide path: M fastest -> 8 co-scheduled M-CTAs share W2 slices in L2
    wide_kernel<<<dim3(BATCH / BM, N_OUT / BN, KSPLIT), NTH, SMEM_BYTES>>>(hs, ht, W2, out);
}